// round 1
// baseline (speedup 1.0000x reference)
#include <cuda_runtime.h>
#include <math.h>

#define N_B     8192
#define CONT    62
#define EMB     16
#define FEAT    94
#define KNB     64
#define NH      4
#define NOUT    16
#define HO      64      // NH*NOUT
#define NTHREADS 256
#define FSTR    100     // sFeat row stride (pad: 100 % 32 == 4, avoids bank collisions)

// shared layout (floats):
// sWd   : 6016   (Wd as [f][h*16+o])
// sFeat : 64*100 = 6400
// sHn   : 4096   ([k][ho])
// sComb : 96, sDev : 96
// sE    : 256    ([h][k])
// sHc   : 64, sHCd : 4
// sHO   : 64, sAF : 16, sX2 : 64, sX3 : 32
// total = 17204 floats = 68816 bytes

__global__ __launch_bounds__(NTHREADS) void gat_kernel(
    const float* __restrict__ combin_cont,
    const int*   __restrict__ combin_cat,
    const float* __restrict__ device_cont,
    const int*   __restrict__ device_cat,
    const int*   __restrict__ combin_idx,
    const int*   __restrict__ device_idx,
    const int*   __restrict__ neighbor_idx,
    const float* __restrict__ ce0,
    const float* __restrict__ ce1,
    const float* __restrict__ de0,
    const float* __restrict__ de1,
    const float* __restrict__ Wc,
    const float* __restrict__ bc,
    const float* __restrict__ Wd,
    const float* __restrict__ bd,
    const float* __restrict__ aW,
    const float* __restrict__ ab,
    const float* __restrict__ W1,
    const float* __restrict__ b1,
    const float* __restrict__ W2,
    const float* __restrict__ b2,
    const float* __restrict__ W3,
    const float* __restrict__ b3,
    const float* __restrict__ W4,
    const float* __restrict__ b4,
    float* __restrict__ out)
{
    extern __shared__ float sm[];
    float* sWd   = sm;                  // 6016
    float* sFeat = sWd   + 6016;        // 6400
    float* sHn   = sFeat + 6400;        // 4096
    float* sComb = sHn   + 4096;        // 96
    float* sDev  = sComb + 96;          // 96
    float* sE    = sDev  + 96;          // 256
    float* sHc   = sE    + 256;         // 64
    float* sHCd  = sHc   + 64;          // 4
    float* sHO   = sHCd  + 4;           // 64
    float* sAF   = sHO   + 64;          // 16
    float* sX2   = sAF   + 16;          // 64
    float* sX3   = sX2   + 64;          // 32

    const int b   = blockIdx.x;
    const int tid = threadIdx.x;

    // ---- Phase A: stage Wd into smem as [f][ho] ----
    #pragma unroll 1
    for (int i = tid; i < FEAT * HO; i += NTHREADS) {
        int f = i >> 6, ho = i & 63;
        int h = ho >> 4, o = ho & 15;
        sWd[i] = Wd[(h * FEAT + f) * NOUT + o];
    }

    // ---- Phase B: gather comb_batch / dev_batch feature rows ----
    const int ci = combin_idx[b];
    const int di = device_idx[b];
    if (tid < FEAT) {
        int f = tid;
        float v;
        if (f < CONT)            v = combin_cont[ci * CONT + f];
        else if (f < CONT + EMB) v = ce0[combin_cat[2 * ci]     * EMB + (f - CONT)];
        else                     v = ce1[combin_cat[2 * ci + 1] * EMB + (f - CONT - EMB)];
        sComb[f] = v;
    } else if (tid >= 128 && tid < 128 + FEAT) {
        int f = tid - 128;
        float v;
        if (f < CONT)            v = device_cont[di * CONT + f];
        else if (f < CONT + EMB) v = de0[device_cat[2 * di]     * EMB + (f - CONT)];
        else                     v = de1[device_cat[2 * di + 1] * EMB + (f - CONT - EMB)];
        sDev[f] = v;
    }

    // ---- Phase C: gather 64 neighbor feature rows (warp per neighbor) ----
    {
        const int warp = tid >> 5, lane = tid & 31;
        for (int k = warp; k < KNB; k += 8) {
            int nid = neighbor_idx[b * KNB + k];
            int n0 = device_cat[2 * nid], n1 = device_cat[2 * nid + 1];
            float* dst = sFeat + k * FSTR;
            for (int f = lane; f < FEAT; f += 32) {
                float v;
                if (f < CONT)            v = device_cont[nid * CONT + f];
                else if (f < CONT + EMB) v = de0[n0 * EMB + (f - CONT)];
                else                     v = de1[n1 * EMB + (f - CONT - EMB)];
                dst[f] = v;
            }
        }
    }
    __syncthreads();

    // ---- Phase D: h_c = comb @ Wc + bc  (threads 0..63), then a1-dot ----
    if (tid < HO) {
        int h = tid >> 4, o = tid & 15;
        float acc = bc[h * NOUT + o];
        #pragma unroll 2
        for (int f = 0; f < FEAT; f++)
            acc += sComb[f] * Wc[(h * FEAT + f) * NOUT + o];
        sHc[tid] = acc;
    }
    __syncthreads();
    if (tid < NH) {
        float d = ab[tid];
        #pragma unroll
        for (int o = 0; o < NOUT; o++)
            d += sHc[tid * NOUT + o] * aW[tid * 2 * NOUT + o];
        sHCd[tid] = d;  // hc·a1 + ab  (read after next barrier)
    }

    // ---- Phase E: h_n = neibr(64x94) @ Wd(94x64) + bd ; 4x4 tile/thread ----
    {
        const int tx = tid & 15;        // ho-block
        const int ty = tid >> 4;        // k-block
        const int ho0 = tx * 4;
        const int k0  = ty * 4;
        float acc[4][4];
        #pragma unroll
        for (int j = 0; j < 4; j++) {
            int ho = ho0 + j;
            float bv = bd[(ho >> 4) * NOUT + (ho & 15)];
            acc[0][j] = bv; acc[1][j] = bv; acc[2][j] = bv; acc[3][j] = bv;
        }
        const float* fp = sFeat + k0 * FSTR;
        #pragma unroll 2
        for (int f = 0; f < FEAT; f++) {
            float4 wv = *(const float4*)&sWd[f * HO + ho0];
            float a0 = fp[f];
            float a1v = fp[FSTR + f];
            float a2v = fp[2 * FSTR + f];
            float a3v = fp[3 * FSTR + f];
            acc[0][0] += a0  * wv.x; acc[0][1] += a0  * wv.y; acc[0][2] += a0  * wv.z; acc[0][3] += a0  * wv.w;
            acc[1][0] += a1v * wv.x; acc[1][1] += a1v * wv.y; acc[1][2] += a1v * wv.z; acc[1][3] += a1v * wv.w;
            acc[2][0] += a2v * wv.x; acc[2][1] += a2v * wv.y; acc[2][2] += a2v * wv.z; acc[2][3] += a2v * wv.w;
            acc[3][0] += a3v * wv.x; acc[3][1] += a3v * wv.y; acc[3][2] += a3v * wv.z; acc[3][3] += a3v * wv.w;
        }
        #pragma unroll
        for (int i = 0; i < 4; i++) {
            float4 o4 = make_float4(acc[i][0], acc[i][1], acc[i][2], acc[i][3]);
            *(float4*)&sHn[(k0 + i) * HO + ho0] = o4;
        }
    }
    __syncthreads();

    // ---- Phase E2: e[h][k] = hc·a1 + ab + h_n[k,h,:]·a2, leaky-relu ----
    {
        int h = tid >> 6, k = tid & 63;
        float s = sHCd[h];
        #pragma unroll
        for (int o = 0; o < NOUT; o++)
            s += sHn[k * HO + h * NOUT + o] * aW[h * 2 * NOUT + NOUT + o];
        sE[h * KNB + k] = (s >= 0.f) ? s : 0.2f * s;
    }
    __syncthreads();

    // ---- softmax over k per head (warp h) ----
    if (tid < 128) {
        int h = tid >> 5, lane = tid & 31;
        float v0 = sE[h * KNB + lane];
        float v1 = sE[h * KNB + lane + 32];
        float m = fmaxf(v0, v1);
        #pragma unroll
        for (int off = 16; off; off >>= 1) m = fmaxf(m, __shfl_xor_sync(0xffffffffu, m, off));
        float e0 = __expf(v0 - m), e1 = __expf(v1 - m);
        float s = e0 + e1;
        #pragma unroll
        for (int off = 16; off; off >>= 1) s += __shfl_xor_sync(0xffffffffu, s, off);
        float inv = __frcp_rn(s);
        sE[h * KNB + lane]      = e0 * inv;
        sE[h * KNB + lane + 32] = e1 * inv;
    }
    __syncthreads();

    // ---- Phase F: head_out[ho] = elu( sum_k attn[h][k]*h_n[k][ho] ) ----
    if (tid < HO) {
        int h = tid >> 4;
        float s = 0.f;
        #pragma unroll 4
        for (int k = 0; k < KNB; k++)
            s += sE[h * KNB + k] * sHn[k * HO + tid];
        sHO[tid] = (s > 0.f) ? s : (__expf(s) - 1.f);
    }
    __syncthreads();

    // ---- Phase G: attn_feats = head_out(64) @ W1(64x16) + b1 ----
    if (tid < NOUT) {
        float s = b1[tid];
        #pragma unroll 4
        for (int i = 0; i < HO; i++)
            s += sHO[i] * W1[i * NOUT + tid];
        sAF[tid] = s;
    }
    __syncthreads();

    // ---- Phase H: x2 = relu(fusion(204) @ W2(204x64) + b2) ----
    if (tid < 64) {
        float s = b2[tid];
        #pragma unroll 2
        for (int f = 0; f < FEAT; f++) s += sComb[f] * W2[f * 64 + tid];
        #pragma unroll 2
        for (int f = 0; f < FEAT; f++) s += sDev[f]  * W2[(FEAT + f) * 64 + tid];
        #pragma unroll
        for (int f = 0; f < NOUT; f++) s += sAF[f]   * W2[(2 * FEAT + f) * 64 + tid];
        sX2[tid] = fmaxf(s, 0.f);
    }
    __syncthreads();

    // ---- Phase I: x3 = relu(x2 @ W3(64x32) + b3) ----
    if (tid < 32) {
        float s = b3[tid];
        #pragma unroll 4
        for (int j = 0; j < 64; j++) s += sX2[j] * W3[j * 32 + tid];
        sX3[tid] = fmaxf(s, 0.f);
    }
    __syncthreads();

    // ---- Phase J: out = sigmoid(x3 @ W4(32x1) + b4) ----
    if (tid < 32) {
        float v = sX3[tid] * W4[tid];
        #pragma unroll
        for (int off = 16; off; off >>= 1) v += __shfl_xor_sync(0xffffffffu, v, off);
        if (tid == 0) out[b] = 1.f / (1.f + __expf(-(v + b4[0])));
    }
}

extern "C" void kernel_launch(void* const* d_in, const int* in_sizes, int n_in,
                              void* d_out, int out_size)
{
    (void)in_sizes; (void)n_in; (void)out_size;
    const int smem_bytes = 17204 * 4;  // 68816
    cudaFuncSetAttribute(gat_kernel, cudaFuncAttributeMaxDynamicSharedMemorySize, smem_bytes);

    gat_kernel<<<N_B, NTHREADS, smem_bytes>>>(
        (const float*)d_in[0],   // combin_cont
        (const int*)  d_in[1],   // combin_cat
        (const float*)d_in[2],   // device_cont
        (const int*)  d_in[3],   // device_cat
        (const int*)  d_in[4],   // combin_idx
        (const int*)  d_in[5],   // device_idx
        (const int*)  d_in[6],   // neighbor_idx
        (const float*)d_in[7],   // ce0
        (const float*)d_in[8],   // ce1
        (const float*)d_in[9],   // de0
        (const float*)d_in[10],  // de1
        (const float*)d_in[11],  // Wc
        (const float*)d_in[12],  // bc
        (const float*)d_in[13],  // Wd
        (const float*)d_in[14],  // bd
        (const float*)d_in[15],  // aW
        (const float*)d_in[16],  // ab
        (const float*)d_in[17],  // W1
        (const float*)d_in[18],  // b1
        (const float*)d_in[19],  // W2
        (const float*)d_in[20],  // b2
        (const float*)d_in[21],  // W3
        (const float*)d_in[22],  // b3
        (const float*)d_in[23],  // W4
        (const float*)d_in[24],  // b4
        (float*)d_out);
}

// round 4
// speedup vs baseline: 3.8320x; 3.8320x over previous
#include <cuda_runtime.h>
#include <math.h>

#define N_B      8192
#define CONT     62
#define EMB      16
#define FEAT     94
#define FPAD     96
#define KNB      64
#define NH       4
#define NOUT     16
#define HO       64
#define NTHREADS 256
#define FSTR     100   // sFeat row stride in floats (float4-aligned, conflict-friendly)

// ---------------- folded-weight scratch (written by prep_kernel each launch) ----
__device__ float g_wd2[NH * FPAD];     // Wd[h] @ a2[h], f-padded with zeros
__device__ float g_vch[NH * FPAD];     // Wc[h] @ a1[h], f-padded with zeros
__device__ float g_ech[NH];            // bc·a1 + ab + bd·a2
__device__ float g_Wdp[FPAD * HO];     // Wd as [f][h*16+o], zero rows f>=94
__device__ float g_Wfus[(2 * FEAT + HO) * 64];  // 252x64: [W2a; W2b; W1@W2c]
__device__ float g_b2f[64];            // b2 + b1@W2c

__global__ __launch_bounds__(NTHREADS) void prep_kernel(
    const float* __restrict__ Wc, const float* __restrict__ bc,
    const float* __restrict__ Wd, const float* __restrict__ bd,
    const float* __restrict__ aW, const float* __restrict__ ab,
    const float* __restrict__ W1, const float* __restrict__ b1,
    const float* __restrict__ W2, const float* __restrict__ b2)
{
    const int tid = threadIdx.x;

    for (int idx = tid; idx < NH * FPAD; idx += NTHREADS) {
        int h = idx / FPAD, f = idx % FPAD;
        float s2 = 0.f, s1 = 0.f;
        if (f < FEAT) {
            #pragma unroll
            for (int o = 0; o < NOUT; o++) {
                s2 += Wd[(h * FEAT + f) * NOUT + o] * aW[h * 2 * NOUT + NOUT + o];
                s1 += Wc[(h * FEAT + f) * NOUT + o] * aW[h * 2 * NOUT + o];
            }
        }
        g_wd2[idx] = s2;
        g_vch[idx] = s1;
    }
    if (tid < NH) {
        float s = ab[tid];
        #pragma unroll
        for (int o = 0; o < NOUT; o++) {
            s += bc[tid * NOUT + o] * aW[tid * 2 * NOUT + o];
            s += bd[tid * NOUT + o] * aW[tid * 2 * NOUT + NOUT + o];
        }
        g_ech[tid] = s;
    }
    for (int idx = tid; idx < FPAD * HO; idx += NTHREADS) {
        int f = idx >> 6, ho = idx & 63;
        g_Wdp[idx] = (f < FEAT) ? Wd[((ho >> 4) * FEAT + f) * NOUT + (ho & 15)] : 0.f;
    }
    for (int idx = tid; idx < (2 * FEAT + HO) * 64; idx += NTHREADS) {
        int r = idx >> 6, j = idx & 63;
        float v;
        if (r < 2 * FEAT) {
            v = W2[r * 64 + j];
        } else {
            int i = r - 2 * FEAT;
            float s = 0.f;
            #pragma unroll
            for (int t = 0; t < NOUT; t++)
                s += W1[i * NOUT + t] * W2[(2 * FEAT + t) * 64 + j];
            v = s;
        }
        g_Wfus[idx] = v;
    }
    if (tid < 64) {
        float s = b2[tid];
        #pragma unroll
        for (int t = 0; t < NOUT; t++)
            s += b1[t] * W2[(2 * FEAT + t) * 64 + tid];
        g_b2f[tid] = s;
    }
}

// ---------------- main fused kernel: one CTA per batch element -------------------
__global__ __launch_bounds__(NTHREADS) void gat_kernel(
    const float* __restrict__ combin_cont,
    const int*   __restrict__ combin_cat,
    const float* __restrict__ device_cont,
    const int*   __restrict__ device_cat,
    const int*   __restrict__ combin_idx,
    const int*   __restrict__ device_idx,
    const int*   __restrict__ neighbor_idx,
    const float* __restrict__ ce0,
    const float* __restrict__ ce1,
    const float* __restrict__ de0,
    const float* __restrict__ de1,
    const float* __restrict__ bd,
    const float* __restrict__ W3,
    const float* __restrict__ b3,
    const float* __restrict__ W4,
    const float* __restrict__ b4,
    float* __restrict__ out)
{
    __shared__ __align__(16) float sFeat[KNB * FSTR];   // 25600B
    __shared__ __align__(16) float sWd2[NH * FPAD];     // 384 floats
    __shared__ __align__(16) float sM[NH * FPAD];       // pooled features
    __shared__ float sE[NH * KNB];
    __shared__ float sEbase[NH];
    __shared__ float sComb[FPAD];
    __shared__ float sDev[FPAD];
    __shared__ float sHO[HO];
    __shared__ float sX2[64];
    __shared__ float sPart[3 * 64];
    __shared__ float sP2[4 * 32];
    __shared__ int   sNid[KNB];
    __shared__ int   sCat0[KNB];
    __shared__ int   sCat1[KNB];

    const int b   = blockIdx.x;
    const int tid = threadIdx.x;
    const int lane = tid & 31;

    // ---- Prologue A: independent loads ----
    for (int idx = tid; idx < NH * FPAD; idx += NTHREADS)
        sWd2[idx] = g_wd2[idx];

    if (tid < KNB) {
        sNid[tid] = neighbor_idx[b * KNB + tid];
    } else if (tid >= 64 && tid < 64 + FEAT) {
        int f = tid - 64;
        int ci = combin_idx[b];
        float v;
        if (f < CONT)            v = combin_cont[ci * CONT + f];
        else if (f < CONT + EMB) v = ce0[combin_cat[2 * ci]     * EMB + (f - CONT)];
        else                     v = ce1[combin_cat[2 * ci + 1] * EMB + (f - CONT - EMB)];
        sComb[f] = v;
    } else if (tid >= 160 && tid < 160 + FEAT) {
        int f = tid - 160;
        int di = device_idx[b];
        float v;
        if (f < CONT)            v = device_cont[di * CONT + f];
        else if (f < CONT + EMB) v = de0[device_cat[2 * di]     * EMB + (f - CONT)];
        else                     v = de1[device_cat[2 * di + 1] * EMB + (f - CONT - EMB)];
        sDev[f] = v;
    }
    __syncthreads();

    // ---- Prologue B: neighbor cat ids + e_base ----
    if (tid < KNB) {
        sCat0[tid] = device_cat[2 * sNid[tid]];
    } else if (tid < 2 * KNB) {
        sCat1[tid - KNB] = device_cat[2 * sNid[tid - KNB] + 1];
    } else if (tid < 160) {
        // warp 4: e_base[h] = comb . vch[h] + ech[h]; 8 lanes per head
        int l = tid - 128;
        int h = l >> 3, sub = l & 7;
        float s = 0.f;
        for (int f = sub; f < FEAT; f += 8)
            s += sComb[f] * g_vch[h * FPAD + f];
        s += __shfl_down_sync(0xffffffffu, s, 4);
        s += __shfl_down_sync(0xffffffffu, s, 2);
        s += __shfl_down_sync(0xffffffffu, s, 1);
        if (sub == 0) sEbase[h] = s + g_ech[h];
    }
    __syncthreads();

    // ---- Gather: 64 neighbor feature rows, warp per row ----
    {
        const int warp = tid >> 5;
        for (int k = warp; k < KNB; k += 8) {
            int nid = sNid[k], n0 = sCat0[k], n1 = sCat1[k];
            float* dst = sFeat + k * FSTR;
            #pragma unroll
            for (int f = lane; f < FPAD; f += 32) {
                float v;
                if (f < CONT)                 v = device_cont[nid * CONT + f];
                else if (f < CONT + EMB)      v = de0[n0 * EMB + (f - CONT)];
                else if (f < FEAT)            v = de1[n1 * EMB + (f - CONT - EMB)];
                else                          v = 0.f;   // pad f=94,95
                dst[f] = v;
            }
        }
    }
    __syncthreads();

    // ---- S1: e[h][k] = feat_k . wd2[h] + e_base[h], leaky-relu ----
    {
        int k = tid & 63, h = tid >> 6;
        const float4* fp = reinterpret_cast<const float4*>(sFeat) + k * (FSTR / 4);
        const float4* wp = reinterpret_cast<const float4*>(sWd2) + h * (FPAD / 4);
        float ax = 0.f, ay = 0.f, az = 0.f, aw = 0.f;
        #pragma unroll
        for (int ff = 0; ff < FPAD / 4; ff++) {
            float4 a = fp[ff];
            float4 w = wp[ff];
            ax += a.x * w.x; ay += a.y * w.y; az += a.z * w.z; aw += a.w * w.w;
        }
        float e = (ax + ay) + (az + aw) + sEbase[h];
        sE[h * KNB + k] = (e >= 0.f) ? e : 0.2f * e;
    }
    __syncthreads();

    // ---- softmax over k per head (warp h) ----
    if (tid < 128) {
        int h = tid >> 5;
        float v0 = sE[h * KNB + lane];
        float v1 = sE[h * KNB + lane + 32];
        float m = fmaxf(v0, v1);
        #pragma unroll
        for (int off = 16; off; off >>= 1) m = fmaxf(m, __shfl_xor_sync(0xffffffffu, m, off));
        float e0 = __expf(v0 - m), e1 = __expf(v1 - m);
        float s = e0 + e1;
        #pragma unroll
        for (int off = 16; off; off >>= 1) s += __shfl_xor_sync(0xffffffffu, s, off);
        float inv = __frcp_rn(s);
        sE[h * KNB + lane]      = e0 * inv;
        sE[h * KNB + lane + 32] = e1 * inv;
    }
    __syncthreads();

    // ---- S2: pooled features m[h][f] = sum_k attn[h][k] * feat[k][f] ----
    #pragma unroll
    for (int pass = 0; pass < 2; pass++) {
        int idx = pass * NTHREADS + tid;
        if (idx < NH * FPAD) {
            int h = idx / FPAD, f = idx % FPAD;
            float s = 0.f;
            const float* ep = sE + h * KNB;
            const float* fp = sFeat + f;
            #pragma unroll 8
            for (int k = 0; k < KNB; k++)
                s += ep[k] * fp[k * FSTR];
            sM[idx] = s;
        }
    }
    __syncthreads();

    // ---- S3 (threads 0-63): head_out = elu(m[h] @ Wd[h] + bd) || fusion partials ----
    if (tid < HO) {
        int h = tid >> 4;
        float s = bd[tid];
        const float* mp = sM + h * FPAD;
        #pragma unroll 2
        for (int f = 0; f < FEAT; f++)
            s += mp[f] * g_Wdp[f * HO + tid];
        sHO[tid] = (s > 0.f) ? s : (__expf(s) - 1.f);
    } else {
        // threads 64-255: comb/dev part of fusion layer (3 chunks of ~63 rows)
        int t = tid - 64;
        int c = t >> 6, j = t & 63;
        int r0 = c * 63;
        int r1 = (c == 2) ? 2 * FEAT : r0 + 63;
        float s = 0.f;
        for (int r = r0; r < r1; r++) {
            float fv = (r < FEAT) ? sComb[r] : sDev[r - FEAT];
            s += fv * g_Wfus[r * 64 + j];
        }
        sPart[c * 64 + j] = s;
    }
    __syncthreads();

    // ---- S4 final: x2 = relu(b2f + partials + head_out @ W12) ----
    if (tid < 64) {
        float s = g_b2f[tid] + sPart[tid] + sPart[64 + tid] + sPart[128 + tid];
        #pragma unroll 4
        for (int i = 0; i < HO; i++)
            s += sHO[i] * g_Wfus[(2 * FEAT + i) * 64 + tid];
        sX2[tid] = fmaxf(s, 0.f);
    }
    __syncthreads();

    // ---- S5: x3 = relu(x2 @ W3 + b3) as 4 partial chunks ----
    if (tid < 128) {
        int j = tid & 31, c = tid >> 5;
        float s = 0.f;
        #pragma unroll
        for (int k = c * 16; k < c * 16 + 16; k++)
            s += sX2[k] * W3[k * 32 + j];
        sP2[c * 32 + j] = s;
    }
    __syncthreads();

    if (tid < 32) {
        float x3 = b3[tid] + sP2[tid] + sP2[32 + tid] + sP2[64 + tid] + sP2[96 + tid];
        x3 = fmaxf(x3, 0.f);
        float v = x3 * W4[tid];
        #pragma unroll
        for (int off = 16; off; off >>= 1) v += __shfl_xor_sync(0xffffffffu, v, off);
        if (tid == 0) out[b] = 1.f / (1.f + __expf(-(v + b4[0])));
    }
}

extern "C" void kernel_launch(void* const* d_in, const int* in_sizes, int n_in,
                              void* d_out, int out_size)
{
    (void)in_sizes; (void)n_in; (void)out_size;

    prep_kernel<<<1, NTHREADS>>>(
        (const float*)d_in[11],  // Wc
        (const float*)d_in[12],  // bc
        (const float*)d_in[13],  // Wd
        (const float*)d_in[14],  // bd
        (const float*)d_in[15],  // aW
        (const float*)d_in[16],  // ab
        (const float*)d_in[17],  // W1
        (const float*)d_in[18],  // b1
        (const float*)d_in[19],  // W2
        (const float*)d_in[20]); // b2

    gat_kernel<<<N_B, NTHREADS>>>(
        (const float*)d_in[0],   // combin_cont
        (const int*)  d_in[1],   // combin_cat
        (const float*)d_in[2],   // device_cont
        (const int*)  d_in[3],   // device_cat
        (const int*)  d_in[4],   // combin_idx
        (const int*)  d_in[5],   // device_idx
        (const int*)  d_in[6],   // neighbor_idx
        (const float*)d_in[7],   // ce0
        (const float*)d_in[8],   // ce1
        (const float*)d_in[9],   // de0
        (const float*)d_in[10],  // de1
        (const float*)d_in[14],  // bd
        (const float*)d_in[21],  // W3
        (const float*)d_in[22],  // b3
        (const float*)d_in[23],  // W4
        (const float*)d_in[24],  // b4
        (float*)d_out);
}